// round 8
// baseline (speedup 1.0000x reference)
#include <cuda_runtime.h>
#include <cstdint>

// VoxelPooling: out[n,:] = mean_{k<20} src_feat[idx(n,k), :]
// idx(n,k) = invoxel_map[n,k] (int32), 0 replaced by invoxel_map[n,0].
//
// Inputs: d_in[0] xyz (UNUSED), d_in[1] map int32 [N,20], d_in[2] src_feat f32 [M,16]
// Output: f32 [N,16]
//
// Two sequential passes over disjoint index halves of src_feat (each half =
// 64 MB, L2-resident). Gathers use 256-bit LDG with L2::evict_last (the only
// form this ptxas accepts the hint on) to pin the half-table; the streaming
// map/out traffic is evict-first (__ldcs/__stcs) so it can't displace it.
// Layout: 2 lanes per voxel, each lane owns 8 channels (32 B): one gather
// row = 2 lanes x 32 B = 64 B exact, half the load instructions of R5.

#define FUSE_K 20

// 32-byte gather with L2 evict_last (LDG.256 on sm_100a)
__device__ __forceinline__ void ldg256_evict_last(const float* p, float (&r)[8]) {
    unsigned u0, u1, u2, u3, u4, u5, u6, u7;
    asm volatile("ld.global.nc.L2::evict_last.v8.b32 {%0,%1,%2,%3,%4,%5,%6,%7}, [%8];"
                 : "=r"(u0), "=r"(u1), "=r"(u2), "=r"(u3),
                   "=r"(u4), "=r"(u5), "=r"(u6), "=r"(u7)
                 : "l"(p));
    r[0] = __int_as_float(u0); r[1] = __int_as_float(u1);
    r[2] = __int_as_float(u2); r[3] = __int_as_float(u3);
    r[4] = __int_as_float(u4); r[5] = __int_as_float(u5);
    r[6] = __int_as_float(u6); r[7] = __int_as_float(u7);
}

__device__ __forceinline__ void load_indices(const int* __restrict__ invoxel_map,
                                             int v, int (&idx)[FUSE_K])
{
    const int4* m = reinterpret_cast<const int4*>(invoxel_map + (long long)v * FUSE_K);
#pragma unroll
    for (int q = 0; q < FUSE_K / 4; q++) {
        int4 p = __ldcs(&m[q]);          // streaming: read once per pass
        idx[q * 4 + 0] = p.x;
        idx[q * 4 + 1] = p.y;
        idx[q * 4 + 2] = p.z;
        idx[q * 4 + 3] = p.w;
    }
    int first = idx[0];
#pragma unroll
    for (int k = 0; k < FUSE_K; k++)
        idx[k] = (idx[k] == 0) ? first : idx[k];
}

__device__ __forceinline__ void gather_half(const float* __restrict__ src_feat,
                                            const int (&idx)[FUSE_K],
                                            int cp, int lo, int hi, float (&acc)[8])
{
#pragma unroll
    for (int k = 0; k < FUSE_K; k++) {
        int id = idx[k];
        if (id >= lo && id < hi) {        // predicated; in-range loads independent
            float f[8];
            ldg256_evict_last(src_feat + (long long)id * 16 + cp * 8, f);
#pragma unroll
            for (int j = 0; j < 8; j++) acc[j] += f[j];
        }
    }
}

__global__ __launch_bounds__(256) void voxel_pool_pass1(
    const int* __restrict__ invoxel_map,
    const float* __restrict__ src_feat,
    float4* __restrict__ out,
    int N, int half)
{
    int t = blockIdx.x * blockDim.x + threadIdx.x;
    int v  = t >> 1;          // voxel
    int cp = t & 1;           // which 32B half of the 16 channels
    if (v >= N) return;

    int idx[FUSE_K];
    load_indices(invoxel_map, v, idx);

    float acc[8] = {0.f, 0.f, 0.f, 0.f, 0.f, 0.f, 0.f, 0.f};
    gather_half(src_feat, idx, cp, 0, half, acc);

    long long o = (long long)v * 4 + cp * 2;
    __stcs(&out[o],     make_float4(acc[0], acc[1], acc[2], acc[3]));
    __stcs(&out[o + 1], make_float4(acc[4], acc[5], acc[6], acc[7]));
}

__global__ __launch_bounds__(256) void voxel_pool_pass2(
    const int* __restrict__ invoxel_map,
    const float* __restrict__ src_feat,
    float4* __restrict__ out,
    int N, int half, int M)
{
    int t = blockIdx.x * blockDim.x + threadIdx.x;
    int v  = t >> 1;
    int cp = t & 1;
    if (v >= N) return;

    int idx[FUSE_K];
    load_indices(invoxel_map, v, idx);

    long long o = (long long)v * 4 + cp * 2;
    float4 p0 = __ldcs(&out[o]);       // partial sums (streaming)
    float4 p1 = __ldcs(&out[o + 1]);
    float acc[8] = {p0.x, p0.y, p0.z, p0.w, p1.x, p1.y, p1.z, p1.w};

    gather_half(src_feat, idx, cp, half, M, acc);

    const float s = 1.0f / (float)FUSE_K;
#pragma unroll
    for (int j = 0; j < 8; j++) acc[j] *= s;

    __stcs(&out[o],     make_float4(acc[0], acc[1], acc[2], acc[3]));
    __stcs(&out[o + 1], make_float4(acc[4], acc[5], acc[6], acc[7]));
}

extern "C" void kernel_launch(void* const* d_in, const int* in_sizes, int n_in,
                              void* d_out, int out_size)
{
    const int*   invoxel_map = (const int*)d_in[1];
    const float* src_feat    = (const float*)d_in[2];
    float4*      out         = (float4*)d_out;

    int N = in_sizes[1] / FUSE_K;     // voxels
    int M = in_sizes[2] / 16;         // src_feat rows
    int half = M / 2;

    int threads_needed = N * 2;       // 2 lanes per voxel
    int block = 256;
    int grid  = (threads_needed + block - 1) / block;

    voxel_pool_pass1<<<grid, block>>>(invoxel_map, src_feat, out, N, half);
    voxel_pool_pass2<<<grid, block>>>(invoxel_map, src_feat, out, N, half, M);
}

// round 9
// speedup vs baseline: 1.0304x; 1.0304x over previous
#include <cuda_runtime.h>
#include <cstdint>

// VoxelPooling: out[n,:] = mean_{k<20} src_feat[idx(n,k), :]
// idx(n,k) = invoxel_map[n,k] (int32), 0 replaced by invoxel_map[n,0].
//
// Inputs: d_in[0] xyz (UNUSED), d_in[1] map int32 [N,20], d_in[2] src_feat f32 [M,16]
// Output: f32 [N,16]
//
// Two sequential passes over disjoint index halves of src_feat (64 MB each,
// L2-resident). R8 showed evict_last hints HURT (DRAM 378->459 MB) - reverted
// to plain __ldg gathers. R5 analysis showed the passes are latency-limited
// (~52% DRAM, ~35% issue, nothing saturated): only ~10 in-range gathers per
// thread. R9: 2 voxels per thread doubles per-warp in-flight loads
// (warps x MLP ~420 -> ~640) to hide L2/DRAM latency.

#define FUSE_K 20

__device__ __forceinline__ void load_indices(const int* __restrict__ invoxel_map,
                                             int v, int (&idx)[FUSE_K])
{
    const int4* m = reinterpret_cast<const int4*>(invoxel_map + (long long)v * FUSE_K);
#pragma unroll
    for (int q = 0; q < FUSE_K / 4; q++) {
        int4 p = __ldcs(&m[q]);          // streaming: read once per pass
        idx[q * 4 + 0] = p.x;
        idx[q * 4 + 1] = p.y;
        idx[q * 4 + 2] = p.z;
        idx[q * 4 + 3] = p.w;
    }
    int first = idx[0];
#pragma unroll
    for (int k = 0; k < FUSE_K; k++)
        idx[k] = (idx[k] == 0) ? first : idx[k];
}

__device__ __forceinline__ void gather_half2(const float4* __restrict__ src_feat,
                                             const int (&idx0)[FUSE_K],
                                             const int (&idx1)[FUSE_K],
                                             bool has1,
                                             int cp, int lo, int hi,
                                             float4& a0, float4& a1)
{
    // Interleave the two voxels' gathers: all in-range loads are independent.
#pragma unroll
    for (int k = 0; k < FUSE_K; k++) {
        int id0 = idx0[k];
        if (id0 >= lo && id0 < hi) {
            float4 f = __ldg(&src_feat[id0 * 4 + cp]);
            a0.x += f.x; a0.y += f.y; a0.z += f.z; a0.w += f.w;
        }
        int id1 = idx1[k];
        if (has1 && id1 >= lo && id1 < hi) {
            float4 f = __ldg(&src_feat[id1 * 4 + cp]);
            a1.x += f.x; a1.y += f.y; a1.z += f.z; a1.w += f.w;
        }
    }
}

template <bool FIRST, bool LAST>
__global__ __launch_bounds__(256, 4) void voxel_pool_pass(
    const int* __restrict__ invoxel_map,
    const float4* __restrict__ src_feat,
    float4* __restrict__ out,
    int N, int lo, int hi)
{
    int t = blockIdx.x * blockDim.x + threadIdx.x;
    int v0 = (t >> 2) * 2;     // first voxel of the pair
    int cp = t & 3;            // float4 chunk of the 16 channels
    if (v0 >= N) return;
    int v1 = v0 + 1;
    bool has1 = (v1 < N);

    int idx0[FUSE_K], idx1[FUSE_K];
    load_indices(invoxel_map, v0, idx0);
    if (has1) load_indices(invoxel_map, v1, idx1);
    else {
#pragma unroll
        for (int k = 0; k < FUSE_K; k++) idx1[k] = 0;
    }

    float4 a0, a1;
    if (FIRST) {
        a0 = make_float4(0.f, 0.f, 0.f, 0.f);
        a1 = make_float4(0.f, 0.f, 0.f, 0.f);
    } else {
        a0 = __ldcs(&out[(long long)v0 * 4 + cp]);
        a1 = has1 ? __ldcs(&out[(long long)v1 * 4 + cp])
                  : make_float4(0.f, 0.f, 0.f, 0.f);
    }

    gather_half2(src_feat, idx0, idx1, has1, cp, lo, hi, a0, a1);

    if (LAST) {
        const float s = 1.0f / (float)FUSE_K;
        a0.x *= s; a0.y *= s; a0.z *= s; a0.w *= s;
        a1.x *= s; a1.y *= s; a1.z *= s; a1.w *= s;
    }
    __stcs(&out[(long long)v0 * 4 + cp], a0);
    if (has1) __stcs(&out[(long long)v1 * 4 + cp], a1);
}

extern "C" void kernel_launch(void* const* d_in, const int* in_sizes, int n_in,
                              void* d_out, int out_size)
{
    const int*    invoxel_map = (const int*)d_in[1];
    const float4* src_feat    = (const float4*)d_in[2];
    float4*       out         = (float4*)d_out;

    int N = in_sizes[1] / FUSE_K;     // voxels
    int M = in_sizes[2] / 16;         // src_feat rows
    int half = M / 2;

    int pairs = (N + 1) / 2;
    int threads_needed = pairs * 4;   // 4 lanes per voxel-pair
    int block = 256;
    int grid  = (threads_needed + block - 1) / block;

    voxel_pool_pass<true,  false><<<grid, block>>>(invoxel_map, src_feat, out, N, 0,    half);
    voxel_pool_pass<false, true ><<<grid, block>>>(invoxel_map, src_feat, out, N, half, M);
}

// round 10
// speedup vs baseline: 1.0634x; 1.0320x over previous
#include <cuda_runtime.h>
#include <cstdint>

// VoxelPooling: out[n,:] = mean_{k<20} src_feat[idx(n,k), :]
// idx(n,k) = invoxel_map[n,k] (int32), 0 replaced by invoxel_map[n,0].
//
// Inputs: d_in[0] xyz (UNUSED), d_in[1] map int32 [N,20], d_in[2] src_feat f32 [M,16]
// Output: f32 [N,16]
//
// Two sequential passes over disjoint index halves of src_feat (64 MB each,
// L2-resident -> gather fills collapse vs the 1.21 GB single-pass thrash).
// KEY FIX vs R5/R9: the per-k range test is BRANCHLESS. R5's `if (in_range)`
// around each gather made ptxas interleave load->use->load (MLP_eff ~2-3,
// only 4.0 TB/s). Here every one of the 20 loads is unconditional: out-of-
// range indices are clamped to row `lo` (L1-resident after first touch) and
// their contribution is zeroed via FFMA weight. Same straight-line 20-load
// body that let R2 saturate DRAM at 6.3 TB/s.

#define FUSE_K 20

template <bool FIRST, bool LAST>
__global__ __launch_bounds__(256) void voxel_pool_pass(
    const int* __restrict__ invoxel_map,   // [N, FUSE_K] int32
    const float4* __restrict__ src_feat,   // [M,4] float4 view of [M,16]
    float4* __restrict__ out,              // [N,4] float4 view of [N,16]
    int N, int lo, int hi)
{
    int t = blockIdx.x * blockDim.x + threadIdx.x;
    int v  = t >> 2;        // voxel
    int cp = t & 3;         // float4 chunk of the 16 channels
    if (v >= N) return;

    // 20 indices via 5x int4 (row stride 80B, 16B aligned). Streaming.
    const int4* m = reinterpret_cast<const int4*>(invoxel_map + (long long)v * FUSE_K);
    int idx[FUSE_K];
#pragma unroll
    for (int q = 0; q < FUSE_K / 4; q++) {
        int4 p = __ldcs(&m[q]);
        idx[q * 4 + 0] = p.x;
        idx[q * 4 + 1] = p.y;
        idx[q * 4 + 2] = p.z;
        idx[q * 4 + 3] = p.w;
    }

    int first = idx[0];
#pragma unroll
    for (int k = 0; k < FUSE_K; k++)
        idx[k] = (idx[k] == 0) ? first : idx[k];

    float4 acc;
    if (FIRST) {
        acc = make_float4(0.f, 0.f, 0.f, 0.f);
    } else {
        acc = __ldcs(&out[(long long)v * 4 + cp]);   // partial sums (streaming)
    }

    // Branchless gather: all 20 loads unconditional -> ptxas front-batches
    // them (deep MLP). Out-of-range lanes read row `lo` (L1 hit) with w=0.
#pragma unroll
    for (int k = 0; k < FUSE_K; k++) {
        int id = idx[k];
        bool in = (id >= lo) && (id < hi);
        int idc = in ? id : lo;
        float w = in ? 1.0f : 0.0f;
        float4 f = __ldg(&src_feat[idc * 4 + cp]);
        acc.x = fmaf(w, f.x, acc.x);
        acc.y = fmaf(w, f.y, acc.y);
        acc.z = fmaf(w, f.z, acc.z);
        acc.w = fmaf(w, f.w, acc.w);
    }

    if (LAST) {
        const float s = 1.0f / (float)FUSE_K;
        acc.x *= s; acc.y *= s; acc.z *= s; acc.w *= s;
    }
    __stcs(&out[(long long)v * 4 + cp], acc);
}

extern "C" void kernel_launch(void* const* d_in, const int* in_sizes, int n_in,
                              void* d_out, int out_size)
{
    const int*    invoxel_map = (const int*)d_in[1];
    const float4* src_feat    = (const float4*)d_in[2];
    float4*       out         = (float4*)d_out;

    int N = in_sizes[1] / FUSE_K;     // voxels
    int M = in_sizes[2] / 16;         // src_feat rows
    int half = M / 2;

    int threads_needed = N * 4;       // 4 lanes per voxel
    int block = 256;
    int grid  = (threads_needed + block - 1) / block;

    voxel_pool_pass<true,  false><<<grid, block>>>(invoxel_map, src_feat, out, N, 0,    half);
    voxel_pool_pass<false, true ><<<grid, block>>>(invoxel_map, src_feat, out, N, half, M);
}

// round 11
// speedup vs baseline: 1.1373x; 1.0694x over previous
#include <cuda_runtime.h>
#include <cstdint>

// VoxelPooling: out[n,:] = mean_{k<20} src_feat[idx(n,k), :]
// idx(n,k) = invoxel_map[n,k] (int32), 0 replaced by invoxel_map[n,0].
//
// Inputs: d_in[0] xyz (UNUSED), d_in[1] map int32 [N,20], d_in[2] src_feat f32 [M,16]
// Output: f32 [N,16]
//
// Two sequential passes over disjoint index halves of src_feat (64 MB each,
// L2-resident). Evolution:
//   R2  single pass: DRAM-bound, 1.21 GB, 190 us.
//   R5  if-guarded split: branches killed load batching, 176 us.
//   R10 clamp+weight split: batching restored (L1 81.5%) but dummy loads
//       added ~2.5M wavefronts/pass and map is read twice -> L1-bound 190 us.
//   R11 (this): PREDICATED asm gather - no branch (batching preserved),
//       predicated-off loads cost zero L1 wavefronts and zero L2/DRAM
//       traffic. Out-of-range contribution adds 0.0f.

#define FUSE_K 20

// Predicated 16B gather: returns zeros when !in, performs no memory access.
__device__ __forceinline__ float4 ldg_pred(const float4* p, int in) {
    float4 r;
    asm("{\n\t"
        ".reg .pred q;\n\t"
        "setp.ne.s32 q, %5, 0;\n\t"
        "mov.f32 %0, 0f00000000;\n\t"
        "mov.f32 %1, 0f00000000;\n\t"
        "mov.f32 %2, 0f00000000;\n\t"
        "mov.f32 %3, 0f00000000;\n\t"
        "@q ld.global.nc.v4.f32 {%0,%1,%2,%3}, [%4];\n\t"
        "}"
        : "=f"(r.x), "=f"(r.y), "=f"(r.z), "=f"(r.w)
        : "l"(p), "r"(in));
    return r;
}

template <bool FIRST, bool LAST>
__global__ __launch_bounds__(256) void voxel_pool_pass(
    const int* __restrict__ invoxel_map,   // [N, FUSE_K] int32
    const float4* __restrict__ src_feat,   // [M,4] float4 view of [M,16]
    float4* __restrict__ out,              // [N,4] float4 view of [N,16]
    int N, int lo, int hi)
{
    int t = blockIdx.x * blockDim.x + threadIdx.x;
    int v  = t >> 2;        // voxel
    int cp = t & 3;         // float4 chunk of the 16 channels
    if (v >= N) return;

    // 20 indices via 5x int4 (row stride 80B, 16B aligned). Streaming.
    const int4* m = reinterpret_cast<const int4*>(invoxel_map + (long long)v * FUSE_K);
    int idx[FUSE_K];
#pragma unroll
    for (int q = 0; q < FUSE_K / 4; q++) {
        int4 p = __ldcs(&m[q]);
        idx[q * 4 + 0] = p.x;
        idx[q * 4 + 1] = p.y;
        idx[q * 4 + 2] = p.z;
        idx[q * 4 + 3] = p.w;
    }

    int first = idx[0];
#pragma unroll
    for (int k = 0; k < FUSE_K; k++)
        idx[k] = (idx[k] == 0) ? first : idx[k];

    float4 acc;
    if (FIRST) {
        acc = make_float4(0.f, 0.f, 0.f, 0.f);
    } else {
        acc = __ldcs(&out[(long long)v * 4 + cp]);   // partial sums (streaming)
    }

    // Predicated gathers: no branches (ptxas keeps the 20 loads batched),
    // out-of-range lanes do NOT issue a memory access.
#pragma unroll
    for (int k = 0; k < FUSE_K; k++) {
        int id = idx[k];
        int in = (id >= lo) && (id < hi);
        float4 f = ldg_pred(&src_feat[id * 4 + cp], in);
        acc.x += f.x;
        acc.y += f.y;
        acc.z += f.z;
        acc.w += f.w;
    }

    if (LAST) {
        const float s = 1.0f / (float)FUSE_K;
        acc.x *= s; acc.y *= s; acc.z *= s; acc.w *= s;
    }
    __stcs(&out[(long long)v * 4 + cp], acc);
}

extern "C" void kernel_launch(void* const* d_in, const int* in_sizes, int n_in,
                              void* d_out, int out_size)
{
    const int*    invoxel_map = (const int*)d_in[1];
    const float4* src_feat    = (const float4*)d_in[2];
    float4*       out         = (float4*)d_out;

    int N = in_sizes[1] / FUSE_K;     // voxels
    int M = in_sizes[2] / 16;         // src_feat rows
    int half = M / 2;

    int threads_needed = N * 4;       // 4 lanes per voxel
    int block = 256;
    int grid  = (threads_needed + block - 1) / block;

    voxel_pool_pass<true,  false><<<grid, block>>>(invoxel_map, src_feat, out, N, 0,    half);
    voxel_pool_pass<false, true ><<<grid, block>>>(invoxel_map, src_feat, out, N, half, M);
}